// round 1
// baseline (speedup 1.0000x reference)
#include <cuda_runtime.h>

// GraphSAGE (GCN-style aggregator), 3 layers, N=100000 nodes, E=1600000 edges,
// F_IN=HID=64, N_CLS=40.
//
// Restructure: ((segsum(h[src]) + h) * inv) @ W^T + b
//            = (segsum(p[src])  + p) * inv + b      with p = h @ W^T
// (per-row scalar inv commutes with the right matmul). So per layer:
//   1) gemm:     p = h @ W^T ; neigh := p   (accumulator initialized w/ self term)
//   2) scatter:  neigh[dst] += p[src]       (red.global.add.v4.f32)
//   3) finalize: h_out = act(neigh * inv + b)

constexpr int NN = 100000;
constexpr int NE = 1600000;

// Scratch (allocation-free rule: __device__ globals). float4 for guaranteed
// 16B alignment of the red.v4 / ld.128 paths.
__device__ float4 g_p[NN * 16];      // projected features, up to 64 f32/row
__device__ float4 g_neigh[NN * 16];  // aggregation accumulator
__device__ float  g_h[NN * 64];      // hidden activations between layers
__device__ int    g_deg[NN];

// ---------------------------------------------------------------- degrees ---
__global__ void deg_zero_k() {
    int i = blockIdx.x * 256 + threadIdx.x;
    if (i < NN) g_deg[i] = 0;
}

__global__ void deg_count_k(const int* __restrict__ dst) {
    int i = blockIdx.x * 256 + threadIdx.x;
    if (i < NE) atomicAdd(&g_deg[dst[i]], 1);
}

// ------------------------------------------------------------------- gemm ---
// p[n, o] = sum_k h[n,k] * W[o,k];  also initializes neigh := p.
// Block (64, 8) = 512 threads; each block handles 64 nodes (8 tiles of 8).
// W held in registers per-thread (one output column per tx), staged through
// padded smem to avoid bank conflicts. hs[ty][k] reads broadcast within warp.
template <int DOUT>
__global__ __launch_bounds__(512) void gemm_k(const float* __restrict__ h,
                                              const float* __restrict__ W) {
    __shared__ float Ws[64 * 65];
    __shared__ float hs[8][64];
    const int tx = threadIdx.x, ty = threadIdx.y;
    const int tid = ty * 64 + tx;

    for (int i = tid; i < DOUT * 64; i += 512)
        Ws[(i >> 6) * 65 + (i & 63)] = W[i];
    __syncthreads();

    float w[64];
    if (tx < DOUT) {
#pragma unroll
        for (int k = 0; k < 64; k++) w[k] = Ws[tx * 65 + k];
    }

    float* gp = reinterpret_cast<float*>(g_p);
    float* gn = reinterpret_cast<float*>(g_neigh);

    const int base = blockIdx.x * 64;
#pragma unroll
    for (int it = 0; it < 8; it++) {
        int n = base + it * 8 + ty;
        __syncthreads();
        if (n < NN) hs[ty][tx] = h[n * 64 + tx];
        __syncthreads();
        if (n < NN && tx < DOUT) {
            float acc = 0.f;
#pragma unroll
            for (int k = 0; k < 64; k++) acc = fmaf(hs[ty][k], w[k], acc);
            gp[n * DOUT + tx] = acc;
            gn[n * DOUT + tx] = acc;
        }
    }
}

// ---------------------------------------------------------------- scatter ---
// neigh[dst] += p[src], rowwise. One float4 (16B) per thread; D4 threads per
// edge. red.global.add.v4.f32 (sm_90+) — 4 floats per reduction op, no return.
template <int D4>
__global__ __launch_bounds__(256) void scatter_k(const int* __restrict__ src,
                                                 const int* __restrict__ dst) {
    const int total = NE * D4;
    int t = blockIdx.x * 256 + threadIdx.x;
    if (t >= total) return;
    int e = t / D4;          // D4 const: strength-reduced by compiler
    int q = t - e * D4;
    int s = __ldg(&src[e]);  // broadcast across the D4 lanes of this edge
    int d = __ldg(&dst[e]);
    float4 v = __ldg(&g_p[s * D4 + q]);
    float4* addr = &g_neigh[d * D4 + q];
    asm volatile("red.global.add.v4.f32 [%0], {%1, %2, %3, %4};"
                 :: "l"(addr), "f"(v.x), "f"(v.y), "f"(v.z), "f"(v.w)
                 : "memory");
}

// --------------------------------------------------------------- finalize ---
// out = act(neigh * inv + b), inv = 1/(deg+1).
template <int D, bool RELU>
__global__ __launch_bounds__(256) void finalize_k(const float* __restrict__ b,
                                                  float* __restrict__ out) {
    int idx = blockIdx.x * 256 + threadIdx.x;
    if (idx >= NN * D) return;
    int n = idx / D;
    int o = idx - n * D;
    float inv = 1.f / (float)(g_deg[n] + 1);
    const float* gn = reinterpret_cast<const float*>(g_neigh);
    float v = fmaf(gn[idx], inv, b[o]);
    out[idx] = RELU ? fmaxf(v, 0.f) : v;
}

// ----------------------------------------------------------------- launch ---
extern "C" void kernel_launch(void* const* d_in, const int* in_sizes, int n_in,
                              void* d_out, int out_size) {
    const float* feats = (const float*)d_in[0];
    const int*   src   = (const int*)d_in[1];
    const int*   dst   = (const int*)d_in[2];
    const float* W0 = (const float*)d_in[3];
    const float* b0 = (const float*)d_in[4];
    const float* W1 = (const float*)d_in[5];
    const float* b1 = (const float*)d_in[6];
    const float* W2 = (const float*)d_in[7];
    const float* b2 = (const float*)d_in[8];
    float* out = (float*)d_out;

    void* h_ptr_v = nullptr;
    cudaGetSymbolAddress(&h_ptr_v, g_h);  // host-side query; graph-safe
    float* h_ptr = (float*)h_ptr_v;

    const int GB_GEMM = (NN + 63) / 64;           // 1563
    const dim3 GEMM_BLK(64, 8);

    // degrees
    deg_zero_k<<<(NN + 255) / 256, 256>>>();
    deg_count_k<<<(NE + 255) / 256, 256>>>(dst);

    // layer 0: features(64) -> 64, relu
    gemm_k<64><<<GB_GEMM, GEMM_BLK>>>(feats, W0);
    scatter_k<16><<<(NE * 16 + 255) / 256, 256>>>(src, dst);
    finalize_k<64, true><<<(NN * 64 + 255) / 256, 256>>>(b0, h_ptr);

    // layer 1: 64 -> 64, relu
    gemm_k<64><<<GB_GEMM, GEMM_BLK>>>(h_ptr, W1);
    scatter_k<16><<<(NE * 16 + 255) / 256, 256>>>(src, dst);
    finalize_k<64, true><<<(NN * 64 + 255) / 256, 256>>>(b1, h_ptr);

    // layer 2: 64 -> 40, no act, straight to d_out
    gemm_k<40><<<GB_GEMM, GEMM_BLK>>>(h_ptr, W2);
    scatter_k<10><<<(NE * 10 + 255) / 256, 256>>>(src, dst);
    finalize_k<40, false><<<(NN * 40 + 255) / 256, 256>>>(b2, out);
}

// round 2
// speedup vs baseline: 1.5190x; 1.5190x over previous
#include <cuda_runtime.h>

// GraphSAGE 3-layer GCN aggregator. N=100000, E=1600000, 64->64->64->40.
//
// Restructure: ((segsum(h[src]) + h) * inv) @ W^T + b
//            = (segsum(p[src])  + p) * inv + b   with p = h @ W^T
// Pipeline (per call):
//   deg -> exclusive scan -> CSR fill (esrc sorted by dst)
//   k0: p0 = feats @ W0^T
//   k1: h1 = relu((gather p0 + self)*inv + b0); p1 = h1 @ W1^T   (fused)
//   k2: h2 = relu((gather p1 + self)*inv + b1); p2 = h2 @ W2^T   (fused)
//   k3: out = (gather p2 + self)*inv + b2                         (no proj)
// Gather is CSR-based (no atomics): 16 lanes/node, float4/lane.

constexpr int NN = 100000;
constexpr int NE = 1600000;
constexpr int NB = (NN + 1023) / 1024;  // 98 scan blocks

__device__ float g_pA[NN * 64];
__device__ float g_pB[NN * 64];
__device__ int   g_deg[NN];
__device__ int   g_off[NN + 1];
__device__ int   g_cur[NN];
__device__ int   g_esrc[NE];
__device__ int   g_bsum[NB];
__device__ int   g_boff[NB];

// ---------------------------------------------------------------- degrees ---
__global__ void deg_zero_k() {
    int i = blockIdx.x * 256 + threadIdx.x;
    if (i < NN) g_deg[i] = 0;
}

__global__ void deg_count_k(const int* __restrict__ dst) {
    int i = blockIdx.x * 256 + threadIdx.x;
    if (i < NE) atomicAdd(&g_deg[dst[i]], 1);
}

// ------------------------------------------------------------------- scan ---
__global__ __launch_bounds__(1024) void scan_bsum_k() {
    int i = blockIdx.x * 1024 + threadIdx.x;
    int v = (i < NN) ? g_deg[i] : 0;
#pragma unroll
    for (int o = 16; o; o >>= 1) v += __shfl_down_sync(~0u, v, o);
    __shared__ int ws[32];
    if ((threadIdx.x & 31) == 0) ws[threadIdx.x >> 5] = v;
    __syncthreads();
    if (threadIdx.x < 32) {
        int s = ws[threadIdx.x];
#pragma unroll
        for (int o = 16; o; o >>= 1) s += __shfl_down_sync(~0u, s, o);
        if (threadIdx.x == 0) g_bsum[blockIdx.x] = s;
    }
}

__global__ void scan_partials_k() {  // 1 block x 128 (NB=98 <= 128)
    int t = threadIdx.x;
    int v = (t < NB) ? g_bsum[t] : 0;
    int lane = t & 31, w = t >> 5;
    int x = v;
#pragma unroll
    for (int o = 1; o < 32; o <<= 1) {
        int y = __shfl_up_sync(~0u, x, o);
        if (lane >= o) x += y;
    }
    __shared__ int wsum[4];
    if (lane == 31) wsum[w] = x;
    __syncthreads();
    int add = 0;
    for (int j = 0; j < w; j++) add += wsum[j];
    if (t < NB) g_boff[t] = x + add - v;  // exclusive
}

__global__ __launch_bounds__(1024) void scan_write_k() {
    int i = blockIdx.x * 1024 + threadIdx.x;
    int v = (i < NN) ? g_deg[i] : 0;
    int lane = threadIdx.x & 31, w = threadIdx.x >> 5;
    int x = v;
#pragma unroll
    for (int o = 1; o < 32; o <<= 1) {
        int y = __shfl_up_sync(~0u, x, o);
        if (lane >= o) x += y;
    }
    __shared__ int ws[32], sws[32];
    if (lane == 31) ws[w] = x;
    __syncthreads();
    if (threadIdx.x < 32) {
        int s = ws[threadIdx.x];
        int xx = s;
#pragma unroll
        for (int o = 1; o < 32; o <<= 1) {
            int y = __shfl_up_sync(~0u, xx, o);
            if (lane >= o) xx += y;
        }
        sws[threadIdx.x] = xx - s;  // exclusive warp prefix
    }
    __syncthreads();
    int incl = x + sws[w] + g_boff[blockIdx.x];
    int excl = incl - v;
    if (i < NN) {
        g_off[i] = excl;
        g_cur[i] = excl;
        if (i == NN - 1) g_off[NN] = incl;
    }
}

// ------------------------------------------------------------------- fill ---
__global__ void fill_k(const int* __restrict__ src, const int* __restrict__ dst) {
    int e = blockIdx.x * 256 + threadIdx.x;
    if (e < NE) {
        int d = dst[e];
        int pos = atomicAdd(&g_cur[d], 1);
        g_esrc[pos] = src[e];
    }
}

// ------------------------------------------------------------------- gemm ---
// p[n,o] = sum_k h[n,k] * W[o,k]  (k0: initial projection of raw features)
__global__ __launch_bounds__(512) void gemm_k(const float* __restrict__ h,
                                              const float* __restrict__ W,
                                              float* __restrict__ p) {
    __shared__ float Ws[64 * 65];
    __shared__ float hs[8][64];
    const int tx = threadIdx.x, ty = threadIdx.y;
    const int tid = ty * 64 + tx;
    for (int i = tid; i < 64 * 64; i += 512)
        Ws[(i >> 6) * 65 + (i & 63)] = W[i];
    __syncthreads();
    float w[64];
#pragma unroll
    for (int k = 0; k < 64; k++) w[k] = Ws[tx * 65 + k];

    const int base = blockIdx.x * 64;
#pragma unroll
    for (int it = 0; it < 8; it++) {
        int n = base + it * 8 + ty;
        __syncthreads();
        if (n < NN) hs[ty][tx] = h[n * 64 + tx];
        __syncthreads();
        if (n < NN) {
            float acc = 0.f;
#pragma unroll
            for (int k = 0; k < 64; k++) acc = fmaf(hs[ty][k], w[k], acc);
            p[n * 64 + tx] = acc;
        }
    }
}

// ---------------------------------------------------------- fused layer -----
// Per node: gather-sum p[src] rows (CSR), + self, *inv, +b, (relu),
// then optionally project h @ W^T -> pout (width DO). If DO==0, write h (width
// DG) straight to pout. 256 threads = 16 node-groups x 16 lanes, float4/lane.
template <int DG, int DO, bool RELU>
__global__ __launch_bounds__(256) void layer_k(const float* __restrict__ bv,
                                               const float* __restrict__ W,
                                               const float* __restrict__ pin,
                                               float* __restrict__ pout) {
    constexpr int L4 = DG / 4;
    __shared__ __align__(16) float Ws[64 * 65];
    __shared__ __align__(16) float hs[16][68];
    const int tid = threadIdx.x;

    if (DO > 0) {
        for (int i = tid; i < DO * 64; i += 256)
            Ws[(i >> 6) * 65 + (i & 63)] = W[i];
    }

    const int g = tid >> 4;
    const int q = tid & 15;
    const int node = blockIdx.x * 16 + g;
    const float4* pin4 = reinterpret_cast<const float4*>(pin);

    if (node < NN && q < L4) {
        int s0 = g_off[node], s1 = g_off[node + 1];
        float inv = 1.f / (float)(s1 - s0 + 1);
        float4 a0 = __ldg(&pin4[node * L4 + q]);  // self term
        float4 a1 = make_float4(0.f, 0.f, 0.f, 0.f);
        int e = s0;
        for (; e + 1 < s1; e += 2) {
            int sa = __ldg(&g_esrc[e]);
            int sb = __ldg(&g_esrc[e + 1]);
            float4 va = __ldg(&pin4[sa * L4 + q]);
            float4 vb = __ldg(&pin4[sb * L4 + q]);
            a0.x += va.x; a0.y += va.y; a0.z += va.z; a0.w += va.w;
            a1.x += vb.x; a1.y += vb.y; a1.z += vb.z; a1.w += vb.w;
        }
        if (e < s1) {
            int sa = __ldg(&g_esrc[e]);
            float4 va = __ldg(&pin4[sa * L4 + q]);
            a0.x += va.x; a0.y += va.y; a0.z += va.z; a0.w += va.w;
        }
        a0.x += a1.x; a0.y += a1.y; a0.z += a1.z; a0.w += a1.w;
        float4 bb = __ldg(&reinterpret_cast<const float4*>(bv)[q]);
        float4 r;
        r.x = fmaf(a0.x, inv, bb.x);
        r.y = fmaf(a0.y, inv, bb.y);
        r.z = fmaf(a0.z, inv, bb.z);
        r.w = fmaf(a0.w, inv, bb.w);
        if (RELU) {
            r.x = fmaxf(r.x, 0.f); r.y = fmaxf(r.y, 0.f);
            r.z = fmaxf(r.z, 0.f); r.w = fmaxf(r.w, 0.f);
        }
        if (DO == 0) {
            reinterpret_cast<float4*>(pout)[node * L4 + q] = r;
        } else {
            reinterpret_cast<float4*>(&hs[g][0])[q] = r;
        }
    }

    if (DO > 0) {
        __syncthreads();
        constexpr int TOT = 16 * DO;
#pragma unroll
        for (int r = 0; r < (TOT + 255) / 256; r++) {
            int oi = r * 256 + tid;
            if (oi < TOT) {
                int gg = oi / DO;
                int o = oi - gg * DO;
                int gn = blockIdx.x * 16 + gg;
                if (gn < NN) {
                    float acc = 0.f;
#pragma unroll
                    for (int k = 0; k < 64; k++)
                        acc = fmaf(hs[gg][k], Ws[o * 65 + k], acc);
                    pout[gn * DO + o] = acc;
                }
            }
        }
    }
}

// ----------------------------------------------------------------- launch ---
extern "C" void kernel_launch(void* const* d_in, const int* in_sizes, int n_in,
                              void* d_out, int out_size) {
    const float* feats = (const float*)d_in[0];
    const int*   src   = (const int*)d_in[1];
    const int*   dst   = (const int*)d_in[2];
    const float* W0 = (const float*)d_in[3];
    const float* b0 = (const float*)d_in[4];
    const float* W1 = (const float*)d_in[5];
    const float* b1 = (const float*)d_in[6];
    const float* W2 = (const float*)d_in[7];
    const float* b2 = (const float*)d_in[8];
    float* out = (float*)d_out;

    void *pA_v = nullptr, *pB_v = nullptr;
    cudaGetSymbolAddress(&pA_v, g_pA);
    cudaGetSymbolAddress(&pB_v, g_pB);
    float* pA = (float*)pA_v;
    float* pB = (float*)pB_v;

    // CSR build
    deg_zero_k<<<(NN + 255) / 256, 256>>>();
    deg_count_k<<<(NE + 255) / 256, 256>>>(dst);
    scan_bsum_k<<<NB, 1024>>>();
    scan_partials_k<<<1, 128>>>();
    scan_write_k<<<NB, 1024>>>();
    fill_k<<<(NE + 255) / 256, 256>>>(src, dst);

    const int GB_L = (NN + 15) / 16;  // 6250

    // k0: p0 = feats @ W0^T
    gemm_k<<<(NN + 63) / 64, dim3(64, 8)>>>(feats, W0, pA);
    // k1: h1 = relu(agg(p0)*inv + b0); p1 = h1 @ W1^T
    layer_k<64, 64, true><<<GB_L, 256>>>(b0, W1, pA, pB);
    // k2: h2 = relu(agg(p1)*inv + b1); p2 = h2 @ W2^T (40-wide)
    layer_k<64, 40, true><<<GB_L, 256>>>(b1, W2, pB, pA);
    // k3: out = agg(p2)*inv + b2
    layer_k<40, 0, false><<<GB_L, 256>>>(b2, nullptr, pA, out);
}